// round 12
// baseline (speedup 1.0000x reference)
#include <cuda_runtime.h>
#include <math.h>

#define DEG2RAD_F 0.017453292519943295f
#define HALF_D2R  0.008726646259971648f
#define INV_SQRT_D 0.08838834764831845f

typedef unsigned long long ull;

// scratch
__device__ float g_S[1024 * 50 * 128];   // attn @ V per batch
__device__ float g_Mt[128 * 128];        // Mt[j][k] = sum_d Wq[d][k]*Wk[d][j]

// ---- packed f32x2 helpers (SASS FFMA2 — PTX-only) ----
__device__ __forceinline__ ull fma2(ull a, ull b, ull c) {
    ull d;
    asm("fma.rn.f32x2 %0, %1, %2, %3;" : "=l"(d) : "l"(a), "l"(b), "l"(c));
    return d;
}
__device__ __forceinline__ ull pack2(float lo, float hi) {
    ull d;
    asm("mov.b64 %0, {%1, %2};" : "=l"(d) : "r"(__float_as_uint(lo)), "r"(__float_as_uint(hi)));
    return d;
}
__device__ __forceinline__ float unpack_sum(ull a) {
    unsigned lo, hi;
    asm("mov.b64 {%0, %1}, %2;" : "=r"(lo), "=r"(hi) : "l"(a));
    return __uint_as_float(lo) + __uint_as_float(hi);
}

// ---- cheap math (all coords within ~1.6 deg box) ----
__device__ __forceinline__ float sin_small(float h) {
    float hh = h * h;
    return h * fmaf(hh, fmaf(hh, 8.3333333e-3f, -0.16666667f), 1.0f);
}
__device__ __forceinline__ float cos_small(float h) {
    float hh = h * h;
    return fmaf(hh, fmaf(hh, 4.1666668e-2f, -0.5f), 1.0f);
}
__device__ __forceinline__ float sqrt_approx(float a) {
    float r;
    asm("sqrt.approx.f32 %0, %1;" : "=f"(r) : "f"(a));
    return r;
}
__device__ __forceinline__ float hav_km(float dlh, float dloh, float cc) {
    float s1 = sin_small(dlh), s2 = sin_small(dloh);
    float a = fmaf(cc, s2 * s2, s1 * s1);
    return sqrt_approx(a) * fmaf(a, 2123.6667f, 12742.0f);
}
__device__ __forceinline__ float interp2(const float2* __restrict__ t, float x) {
    x = fminf(x, 62.999996f);
    int k = (int)x;
    float f = x - (float)k;
    float2 p = t[k];
    return fmaf(f, p.y - p.x, p.x);
}

// ---------------- kernel M: Mt[j][k] = sum_d Wq[d][k] * Wk[d][j] ----------------
__global__ void __launch_bounds__(128)
stan_kM(const float* __restrict__ Wq, const float* __restrict__ Wk) {
    const int j = blockIdx.x;
    const int k = threadIdx.x;
    float acc = 0.f;
#pragma unroll 8
    for (int d = 0; d < 128; d++)
        acc = fmaf(Wq[d * 128 + k], Wk[d * 128 + j], acc);
    g_Mt[j * 128 + k] = acc;
}

// out[n][d] = sum_k sx[n][k]*W[d][k], W staged through smem in 16-k chunks.
__device__ __forceinline__ void gemm_staged(const float* __restrict__ gW,
                                            const float* __restrict__ sx,
                                            float* __restrict__ sW,
                                            float* __restrict__ out,
                                            int d, int half, int tid) {
    ull acc2[25];
#pragma unroll
    for (int i = 0; i < 25; i++) acc2[i] = 0ull;
#pragma unroll 1
    for (int c = 0; c < 8; c++) {
        const int kc = c * 16;
        __syncthreads();   // prior chunk's LDS reads done before overwrite
        {   // copy W[:, kc:kc+16] -> sW, coalesced float4
            int idx = tid;
#pragma unroll
            for (int rep = 0; rep < 2; rep++, idx += 256) {
                int dd = idx >> 2, j = (idx & 3) * 4;
                float4 v = *(const float4*)(gW + dd * 128 + kc + j);
                *(float4*)(sW + dd * 20 + j) = v;
            }
        }
        __syncthreads();
#pragma unroll
        for (int k0 = 0; k0 < 16; k0 += 8) {
            ulonglong2 w0 = *(const ulonglong2*)(sW + d * 20 + k0);
            ulonglong2 w1 = *(const ulonglong2*)(sW + d * 20 + k0 + 4);
#pragma unroll
            for (int i = 0; i < 25; i++) {
                const float* xr = sx + (half + 2 * i) * 132 + kc + k0;
                ulonglong2 x0 = *(const ulonglong2*)xr;
                ulonglong2 x1 = *(const ulonglong2*)(xr + 4);
                ull a = acc2[i];
                a = fma2(x0.x, w0.x, a); a = fma2(x0.y, w0.y, a);
                a = fma2(x1.x, w1.x, a); a = fma2(x1.y, w1.y, a);
                acc2[i] = a;
            }
        }
    }
#pragma unroll
    for (int i = 0; i < 25; i++)
        out[(half + 2 * i) * 132 + d] = unpack_sum(acc2[i]);
}

// ---------------- Kernel 1: per-batch attention, writes S ----------------
// (verbatim R10 version — measured as part of 774us total)
__global__ void __launch_bounds__(256, 1)
stan_k1(const int* __restrict__ poi_idx, const int* __restrict__ hour,
        const float* __restrict__ lat, const float* __restrict__ lon,
        const float* __restrict__ tmin,
        const float* __restrict__ poi_emb, const float* __restrict__ time_emb,
        const float* __restrict__ E_t, const float* __restrict__ E_d,
        const float* __restrict__ Wv) {
    extern __shared__ float sm[];
    float* sU = sm + 6600;
    float* sV = sm + 13200;
    float* sW = sm + 19800;
    float* sA = sm + 22360;
    float2* sEt2 = (float2*)(sm + 24960);
    float2* sEd2 = (float2*)(sm + 25088);
    float* st   = sm + 25216;
    float* slh  = sm + 25280;
    float* sloh = sm + 25344;
    float* scs  = sm + 25408;
    int* spad = (int*)(sm + 25472);
    int* spoi = (int*)(sm + 25536);
    int* shr  = (int*)(sm + 25600);

    const int b = blockIdx.x;
    const int tid = threadIdx.x;

    if (tid < 64) {
        sEt2[tid] = make_float2(E_t[tid], E_t[min(tid + 1, 63)]);
        sEd2[tid] = make_float2(E_d[tid], E_d[min(tid + 1, 63)]);
    }
    if (tid < 50) {
        int p = poi_idx[b * 50 + tid];
        int h = hour[b * 50 + tid];
        int pad = (p < 0);
        spad[tid] = pad;
        spoi[tid] = pad ? 50000 : p;
        shr[tid]  = pad ? 0 : h;
        float la = lat[b * 50 + tid];
        float lo = lon[b * 50 + tid];
        slh[tid]  = la * HALF_D2R;
        sloh[tid] = lo * HALF_D2R;
        scs[tid]  = cos_small(la * DEG2RAD_F);
        st[tid]   = tmin[b * 50 + tid];
    }
    __syncthreads();

    // gather x = poi_emb[poi] + time_emb[hour] into sx (stride 132)
    for (int idx = tid; idx < 6400; idx += 256) {
        int n = idx >> 7, d = idx & 127;
        sm[n * 132 + d] = poi_emb[spoi[n] * 128 + d] + time_emb[shr[n] * 128 + d];
    }

    const int d = tid & 127;
    const int half = tid >> 7;
    // U = x @ Mt^T folds Wq/Wk: scores = U . x (first sync inside covers gather)
    gemm_staged(g_Mt, sm, sW, sU, d, half, tid);
    gemm_staged(Wv,   sm, sW, sV, d, half, tid);
    __syncthreads();

    // scores[n][m] = U[n].x[m]/sqrt(D) + bias(n,m); -inf where pad[m]
    {
        const int m0 = tid & 63;
        const int grp = tid >> 6;
        const int m = (m0 < 50) ? m0 : 0;
        ull acc2[13];
#pragma unroll
        for (int i = 0; i < 13; i++) acc2[i] = 0ull;
        for (int d0 = 0; d0 < 128; d0 += 8) {
            ulonglong2 k0 = *(const ulonglong2*)(sm + m * 132 + d0);
            ulonglong2 k1 = *(const ulonglong2*)(sm + m * 132 + d0 + 4);
            int i = 0;
            for (int n = grp; n < 50; n += 4, i++) {
                const float* ur = sU + n * 132 + d0;
                ulonglong2 u0 = *(const ulonglong2*)ur;
                ulonglong2 u1 = *(const ulonglong2*)(ur + 4);
                ull a = acc2[i];
                a = fma2(u0.x, k0.x, a); a = fma2(u0.y, k0.y, a);
                a = fma2(u1.x, k1.x, a); a = fma2(u1.y, k1.y, a);
                acc2[i] = a;
            }
        }
        if (m0 < 50) {
            float tm = st[m0], lhm = slh[m0], lom = sloh[m0], cm = scs[m0];
            int padm = spad[m0];
            int i = 0;
            for (int n = grp; n < 50; n += 4, i++) {
                float vp = (spad[n] | padm) ? 0.f : 1.f;
                float dt = fabsf(st[n] - tm) * vp;
                float dd = hav_km(lhm - slh[n], lom - sloh[n], scs[n] * cm) * vp;
                float bias = interp2(sEt2, dt * (63.0f / 10080.0f))
                           + interp2(sEd2, dd * (63.0f / 200.0f));
                float sc = fmaf(unpack_sum(acc2[i]), INV_SQRT_D, bias);
                if (padm) sc = -INFINITY;
                sA[n * 52 + m0] = sc;
            }
        }
    }
    __syncthreads();

    // row softmax (warp per row)
    {
        int w = tid >> 5, lane = tid & 31;
        for (int n = w; n < 50; n += 8) {
            float v0 = (lane < 50)      ? sA[n * 52 + lane]      : -INFINITY;
            float v1 = (lane + 32 < 50) ? sA[n * 52 + lane + 32] : -INFINITY;
            float mx = fmaxf(v0, v1);
#pragma unroll
            for (int o = 16; o > 0; o >>= 1)
                mx = fmaxf(mx, __shfl_xor_sync(0xffffffffu, mx, o));
            float e0 = (mx == -INFINITY) ? 0.f : __expf(v0 - mx);
            float e1 = (mx == -INFINITY) ? 0.f : __expf(v1 - mx);
            float s = e0 + e1;
#pragma unroll
            for (int o = 16; o > 0; o >>= 1)
                s += __shfl_xor_sync(0xffffffffu, s, o);
            float inv = (s > 0.f) ? 1.f / s : 0.f;
            if (lane < 50)      sA[n * 52 + lane]      = e0 * inv;
            if (lane + 32 < 50) sA[n * 52 + lane + 32] = e1 * inv;
        }
    }
    __syncthreads();

    // S = attn @ V -> global scratch (packed along m)
    {
        ull acc2[25];
#pragma unroll
        for (int i = 0; i < 25; i++) acc2[i] = 0ull;
        for (int m = 0; m < 50; m += 2) {
            ull v2 = pack2(sV[m * 132 + d], sV[(m + 1) * 132 + d]);
#pragma unroll
            for (int i = 0; i < 25; i++) {
                ull a2 = *(const ull*)(sA + (half + 2 * i) * 52 + m);
                acc2[i] = fma2(a2, v2, acc2[i]);
            }
        }
        float* gS = g_S + b * 6400;
#pragma unroll
        for (int i = 0; i < 25; i++)
            gS[(half + 2 * i) * 128 + d] = unpack_sum(acc2[i]);
    }
}

// ---------------- Kernel 2: matching GEMM + fused softmax-over-n ----------------
// 256 threads, r-tile 128 (2 threads per r, 25 n each), grid (8, 1024).
// S stored PAIR-INTERLEAVED: element (n, d) lives at
//   sS[(n>>1)*264 + (d>>2)*8 + (n&1)*4 + (d&3)]
// so the two halves of a thread pair read addresses 16B apart (same 128B
// line) -> each broadcast S load costs 1 L1tex wavefront instead of 2.
// smem (floats): sS@0 (25*264=6600), sRe@6600 (128*132=16896),
//   Edm2@23496 (128), slh@23624, sloh@23688, scs@23752, spad@23816 -> 23880
__global__ void __launch_bounds__(256, 2)
stan_k2(const int* __restrict__ poi_idx,
        const float* __restrict__ lat, const float* __restrict__ lon,
        const float* __restrict__ cent,
        const float* __restrict__ E_dm,
        const float* __restrict__ region_emb,
        float* __restrict__ out) {
    extern __shared__ float sm[];
    float* sRe = sm + 6600;
    float2* sEdm2 = (float2*)(sm + 23496);
    float* slh  = sm + 23624;
    float* sloh = sm + 23688;
    float* scs  = sm + 23752;
    int* spad   = (int*)(sm + 23816);

    const int b = blockIdx.y;
    const int r0 = blockIdx.x * 128;
    const int tid = threadIdx.x;

    if (tid < 64) sEdm2[tid] = make_float2(E_dm[tid], E_dm[min(tid + 1, 63)]);
    if (tid < 50) {
        float la = lat[b * 50 + tid];
        float lo = lon[b * 50 + tid];
        slh[tid]  = la * HALF_D2R;
        sloh[tid] = lo * HALF_D2R;
        scs[tid]  = cos_small(la * DEG2RAD_F);
        spad[tid] = (poi_idx[b * 50 + tid] < 0);
    }
    // stage S into pair-interleaved layout
    const float* gS = g_S + b * 6400;
    for (int idx = tid; idx < 6400; idx += 256) {
        int n = idx >> 7, d = idx & 127;
        sm[(n >> 1) * 264 + (d >> 2) * 8 + (n & 1) * 4 + (d & 3)] = gS[idx];
    }
    // stage region tile [128 r][128 d] -> sRe stride 132, coalesced float4
    for (int idx = tid; idx < 4096; idx += 256) {
        int row = idx >> 5, c4 = (idx & 31) * 4;
        int r = min(r0 + row, 999);
        float4 v = *(const float4*)(region_emb + r * 128 + c4);
        *(float4*)(sRe + row * 132 + c4) = v;
    }
    __syncthreads();

    const int rl = tid >> 1;
    const int half = tid & 1;
    const int r = r0 + rl;
    const int rc = min(r, 999);
    const float* sp = sm + half * 4;       // (n=2i+half, d-block d0/4) -> sp + i*264 + d0*2
    const float* rrow = sRe + rl * 132;

    ull acc2[25];
#pragma unroll
    for (int i = 0; i < 25; i++) acc2[i] = 0ull;

    for (int d0 = 0; d0 < 128; d0 += 4) {
        ulonglong2 re = *(const ulonglong2*)(rrow + d0);
#pragma unroll
        for (int i = 0; i < 25; i++) {
            ulonglong2 s = *(const ulonglong2*)(sp + i * 264 + d0 * 2);
            ull a = acc2[i];
            a = fma2(s.x, re.x, a);
            a = fma2(s.y, re.y, a);
            acc2[i] = a;
        }
    }

    float accf[25];
#pragma unroll
    for (int i = 0; i < 25; i++) accf[i] = unpack_sum(acc2[i]);

    float cla = cent[rc * 2], clo = cent[rc * 2 + 1];
    float claH = cla * HALF_D2R, cloH = clo * HALF_D2R;
    float cc = cos_small(cla * DEG2RAD_F);
    float mx = -INFINITY;
#pragma unroll
    for (int i = 0; i < 25; i++) {
        int n = 2 * i + half;
        float dd = hav_km(claH - slh[n], cloH - sloh[n], cc * scs[n]);
        float bias = interp2(sEdm2, dd * (63.0f / 200.0f));
        float sc = fmaf(accf[i], INV_SQRT_D, bias);
        if (spad[n]) sc = -INFINITY;
        accf[i] = sc;
        mx = fmaxf(mx, sc);
    }
    mx = fmaxf(mx, __shfl_xor_sync(0xffffffffu, mx, 1));

    float sum = 0.f, ws = 0.f;
    if (mx != -INFINITY) {
#pragma unroll
        for (int i = 0; i < 25; i++) {
            int n = 2 * i + half;
            if (!spad[n]) {
                float e = __expf(accf[i] - mx);
                sum += e;
                ws = fmaf(e, accf[i], ws);
            }
        }
    }
    sum += __shfl_xor_sync(0xffffffffu, sum, 1);
    ws  += __shfl_xor_sync(0xffffffffu, ws, 1);
    if (half == 0 && r < 1000)
        out[b * 1000 + r] = (sum > 0.f) ? ws / sum : 0.f;
}

#define SMEM1_BYTES (25664 * 4)
#define SMEM2_BYTES (23880 * 4)

extern "C" void kernel_launch(void* const* d_in, const int* in_sizes, int n_in,
                              void* d_out, int out_size) {
    const int*   poi  = (const int*)  d_in[0];
    const int*   hr   = (const int*)  d_in[1];
    const float* lat  = (const float*)d_in[2];
    const float* lon  = (const float*)d_in[3];
    const float* tmin = (const float*)d_in[4];
    const float* cent = (const float*)d_in[5];
    const float* pemb = (const float*)d_in[6];
    const float* temb = (const float*)d_in[7];
    const float* Et   = (const float*)d_in[8];
    const float* Ed   = (const float*)d_in[9];
    const float* Edm  = (const float*)d_in[10];
    const float* remb = (const float*)d_in[11];
    const float* Wq   = (const float*)d_in[12];
    const float* Wk   = (const float*)d_in[13];
    const float* Wv   = (const float*)d_in[14];
    float* out = (float*)d_out;

    cudaFuncSetAttribute(stan_k1, cudaFuncAttributeMaxDynamicSharedMemorySize, SMEM1_BYTES);
    cudaFuncSetAttribute(stan_k2, cudaFuncAttributeMaxDynamicSharedMemorySize, SMEM2_BYTES);

    stan_kM<<<128, 128>>>(Wq, Wk);
    stan_k1<<<1024, 256, SMEM1_BYTES>>>(poi, hr, lat, lon, tmin,
                                        pemb, temb, Et, Ed, Wv);
    stan_k2<<<dim3(8, 1024), 256, SMEM2_BYTES>>>(poi, lat, lon, cent, Edm, remb, out);
}

// round 13
// speedup vs baseline: 1.0362x; 1.0362x over previous
#include <cuda_runtime.h>
#include <math.h>

#define DEG2RAD_F 0.017453292519943295f
#define HALF_D2R  0.008726646259971648f
#define INV_SQRT_D 0.08838834764831845f

typedef unsigned long long ull;

// scratch
__device__ float g_S[1024 * 50 * 128];   // attn @ V per batch
__device__ float g_Mt[128 * 128];        // Mt[j][k] = sum_d Wq[d][k]*Wk[d][j]

// ---- packed f32x2 helpers (SASS FFMA2 — PTX-only) ----
__device__ __forceinline__ ull fma2(ull a, ull b, ull c) {
    ull d;
    asm("fma.rn.f32x2 %0, %1, %2, %3;" : "=l"(d) : "l"(a), "l"(b), "l"(c));
    return d;
}
__device__ __forceinline__ ull pack2(float lo, float hi) {
    ull d;
    asm("mov.b64 %0, {%1, %2};" : "=l"(d) : "r"(__float_as_uint(lo)), "r"(__float_as_uint(hi)));
    return d;
}
__device__ __forceinline__ float unpack_sum(ull a) {
    unsigned lo, hi;
    asm("mov.b64 {%0, %1}, %2;" : "=r"(lo), "=r"(hi) : "l"(a));
    return __uint_as_float(lo) + __uint_as_float(hi);
}

// ---- cheap math (all coords within ~1.6 deg box) ----
__device__ __forceinline__ float sin_small(float h) {
    float hh = h * h;
    return h * fmaf(hh, fmaf(hh, 8.3333333e-3f, -0.16666667f), 1.0f);
}
__device__ __forceinline__ float cos_small(float h) {
    float hh = h * h;
    return fmaf(hh, fmaf(hh, 4.1666668e-2f, -0.5f), 1.0f);
}
__device__ __forceinline__ float sqrt_approx(float a) {
    float r;
    asm("sqrt.approx.f32 %0, %1;" : "=f"(r) : "f"(a));
    return r;
}
__device__ __forceinline__ float hav_km(float dlh, float dloh, float cc) {
    float s1 = sin_small(dlh), s2 = sin_small(dloh);
    float a = fmaf(cc, s2 * s2, s1 * s1);
    return sqrt_approx(a) * fmaf(a, 2123.6667f, 12742.0f);
}
__device__ __forceinline__ float interp2(const float2* __restrict__ t, float x) {
    x = fminf(x, 62.999996f);
    int k = (int)x;
    float f = x - (float)k;
    float2 p = t[k];
    return fmaf(f, p.y - p.x, p.x);
}

// ---------------- kernel M: Mt[j][k] = sum_d Wq[d][k] * Wk[d][j] ----------------
__global__ void __launch_bounds__(128)
stan_kM(const float* __restrict__ Wq, const float* __restrict__ Wk) {
    const int j = blockIdx.x;
    const int k = threadIdx.x;
    float acc = 0.f;
#pragma unroll 8
    for (int d = 0; d < 128; d++)
        acc = fmaf(Wq[d * 128 + k], Wk[d * 128 + j], acc);
    g_Mt[j * 128 + k] = acc;
}

// out[n][d] = sum_k sx[n][k]*W[d][k], W staged through smem in 16-k chunks.
__device__ __forceinline__ void gemm_staged(const float* __restrict__ gW,
                                            const float* __restrict__ sx,
                                            float* __restrict__ sW,
                                            float* __restrict__ out,
                                            int d, int half, int tid) {
    ull acc2[25];
#pragma unroll
    for (int i = 0; i < 25; i++) acc2[i] = 0ull;
#pragma unroll 1
    for (int c = 0; c < 8; c++) {
        const int kc = c * 16;
        __syncthreads();   // prior chunk's LDS reads done before overwrite
        {   // copy W[:, kc:kc+16] -> sW, coalesced float4
            int idx = tid;
#pragma unroll
            for (int rep = 0; rep < 2; rep++, idx += 256) {
                int dd = idx >> 2, j = (idx & 3) * 4;
                float4 v = *(const float4*)(gW + dd * 128 + kc + j);
                *(float4*)(sW + dd * 20 + j) = v;
            }
        }
        __syncthreads();
#pragma unroll
        for (int k0 = 0; k0 < 16; k0 += 8) {
            ulonglong2 w0 = *(const ulonglong2*)(sW + d * 20 + k0);
            ulonglong2 w1 = *(const ulonglong2*)(sW + d * 20 + k0 + 4);
#pragma unroll
            for (int i = 0; i < 25; i++) {
                const float* xr = sx + (half + 2 * i) * 132 + kc + k0;
                ulonglong2 x0 = *(const ulonglong2*)xr;
                ulonglong2 x1 = *(const ulonglong2*)(xr + 4);
                ull a = acc2[i];
                a = fma2(x0.x, w0.x, a); a = fma2(x0.y, w0.y, a);
                a = fma2(x1.x, w1.x, a); a = fma2(x1.y, w1.y, a);
                acc2[i] = a;
            }
        }
    }
#pragma unroll
    for (int i = 0; i < 25; i++)
        out[(half + 2 * i) * 132 + d] = unpack_sum(acc2[i]);
}

// ---------------- Kernel 1: per-batch attention, writes S ----------------
// (verbatim R10 version — measured as part of 774us total)
__global__ void __launch_bounds__(256, 1)
stan_k1(const int* __restrict__ poi_idx, const int* __restrict__ hour,
        const float* __restrict__ lat, const float* __restrict__ lon,
        const float* __restrict__ tmin,
        const float* __restrict__ poi_emb, const float* __restrict__ time_emb,
        const float* __restrict__ E_t, const float* __restrict__ E_d,
        const float* __restrict__ Wv) {
    extern __shared__ float sm[];
    float* sU = sm + 6600;
    float* sV = sm + 13200;
    float* sW = sm + 19800;
    float* sA = sm + 22360;
    float2* sEt2 = (float2*)(sm + 24960);
    float2* sEd2 = (float2*)(sm + 25088);
    float* st   = sm + 25216;
    float* slh  = sm + 25280;
    float* sloh = sm + 25344;
    float* scs  = sm + 25408;
    int* spad = (int*)(sm + 25472);
    int* spoi = (int*)(sm + 25536);
    int* shr  = (int*)(sm + 25600);

    const int b = blockIdx.x;
    const int tid = threadIdx.x;

    if (tid < 64) {
        sEt2[tid] = make_float2(E_t[tid], E_t[min(tid + 1, 63)]);
        sEd2[tid] = make_float2(E_d[tid], E_d[min(tid + 1, 63)]);
    }
    if (tid < 50) {
        int p = poi_idx[b * 50 + tid];
        int h = hour[b * 50 + tid];
        int pad = (p < 0);
        spad[tid] = pad;
        spoi[tid] = pad ? 50000 : p;
        shr[tid]  = pad ? 0 : h;
        float la = lat[b * 50 + tid];
        float lo = lon[b * 50 + tid];
        slh[tid]  = la * HALF_D2R;
        sloh[tid] = lo * HALF_D2R;
        scs[tid]  = cos_small(la * DEG2RAD_F);
        st[tid]   = tmin[b * 50 + tid];
    }
    __syncthreads();

    // gather x = poi_emb[poi] + time_emb[hour] into sx (stride 132)
    for (int idx = tid; idx < 6400; idx += 256) {
        int n = idx >> 7, d = idx & 127;
        sm[n * 132 + d] = poi_emb[spoi[n] * 128 + d] + time_emb[shr[n] * 128 + d];
    }

    const int d = tid & 127;
    const int half = tid >> 7;
    // U = x @ Mt^T folds Wq/Wk: scores = U . x (first sync inside covers gather)
    gemm_staged(g_Mt, sm, sW, sU, d, half, tid);
    gemm_staged(Wv,   sm, sW, sV, d, half, tid);
    __syncthreads();

    // scores[n][m] = U[n].x[m]/sqrt(D) + bias(n,m); -inf where pad[m]
    {
        const int m0 = tid & 63;
        const int grp = tid >> 6;
        const int m = (m0 < 50) ? m0 : 0;
        ull acc2[13];
#pragma unroll
        for (int i = 0; i < 13; i++) acc2[i] = 0ull;
        for (int d0 = 0; d0 < 128; d0 += 8) {
            ulonglong2 k0 = *(const ulonglong2*)(sm + m * 132 + d0);
            ulonglong2 k1 = *(const ulonglong2*)(sm + m * 132 + d0 + 4);
            int i = 0;
            for (int n = grp; n < 50; n += 4, i++) {
                const float* ur = sU + n * 132 + d0;
                ulonglong2 u0 = *(const ulonglong2*)ur;
                ulonglong2 u1 = *(const ulonglong2*)(ur + 4);
                ull a = acc2[i];
                a = fma2(u0.x, k0.x, a); a = fma2(u0.y, k0.y, a);
                a = fma2(u1.x, k1.x, a); a = fma2(u1.y, k1.y, a);
                acc2[i] = a;
            }
        }
        if (m0 < 50) {
            float tm = st[m0], lhm = slh[m0], lom = sloh[m0], cm = scs[m0];
            int padm = spad[m0];
            int i = 0;
            for (int n = grp; n < 50; n += 4, i++) {
                float vp = (spad[n] | padm) ? 0.f : 1.f;
                float dt = fabsf(st[n] - tm) * vp;
                float dd = hav_km(lhm - slh[n], lom - sloh[n], scs[n] * cm) * vp;
                float bias = interp2(sEt2, dt * (63.0f / 10080.0f))
                           + interp2(sEd2, dd * (63.0f / 200.0f));
                float sc = fmaf(unpack_sum(acc2[i]), INV_SQRT_D, bias);
                if (padm) sc = -INFINITY;
                sA[n * 52 + m0] = sc;
            }
        }
    }
    __syncthreads();

    // row softmax (warp per row)
    {
        int w = tid >> 5, lane = tid & 31;
        for (int n = w; n < 50; n += 8) {
            float v0 = (lane < 50)      ? sA[n * 52 + lane]      : -INFINITY;
            float v1 = (lane + 32 < 50) ? sA[n * 52 + lane + 32] : -INFINITY;
            float mx = fmaxf(v0, v1);
#pragma unroll
            for (int o = 16; o > 0; o >>= 1)
                mx = fmaxf(mx, __shfl_xor_sync(0xffffffffu, mx, o));
            float e0 = (mx == -INFINITY) ? 0.f : __expf(v0 - mx);
            float e1 = (mx == -INFINITY) ? 0.f : __expf(v1 - mx);
            float s = e0 + e1;
#pragma unroll
            for (int o = 16; o > 0; o >>= 1)
                s += __shfl_xor_sync(0xffffffffu, s, o);
            float inv = (s > 0.f) ? 1.f / s : 0.f;
            if (lane < 50)      sA[n * 52 + lane]      = e0 * inv;
            if (lane + 32 < 50) sA[n * 52 + lane + 32] = e1 * inv;
        }
    }
    __syncthreads();

    // S = attn @ V -> global scratch (packed along m)
    {
        ull acc2[25];
#pragma unroll
        for (int i = 0; i < 25; i++) acc2[i] = 0ull;
        for (int m = 0; m < 50; m += 2) {
            ull v2 = pack2(sV[m * 132 + d], sV[(m + 1) * 132 + d]);
#pragma unroll
            for (int i = 0; i < 25; i++) {
                ull a2 = *(const ull*)(sA + (half + 2 * i) * 52 + m);
                acc2[i] = fma2(a2, v2, acc2[i]);
            }
        }
        float* gS = g_S + b * 6400;
#pragma unroll
        for (int i = 0; i < 25; i++)
            gS[(half + 2 * i) * 128 + d] = unpack_sum(acc2[i]);
    }
}

// ---------------- Kernel 2: matching GEMM + fused softmax-over-n ----------------
// 128 threads (64 pairs); each pair owns r-slots rl and rl+64 -> 2-way
// r-blocking: per d0 step 27 LDS vs 100 FFMA2 per thread (FMA-bound).
// S pair-interleaved: (n,d) at sS[(n>>1)*264 + (d>>2)*8 + (n&1)*4 + (d&3)].
// smem (floats): sS@0 (6600), sRe@6600 (128*132=16896), Edm2@23496 (128),
//   slh@23624, sloh@23688, scs@23752, spad@23816 -> 23880 (95.5 KB)
// launch_bounds(128,2): reg cap 256 (no spill at ~160), 2 blocks/SM.
__global__ void __launch_bounds__(128, 2)
stan_k2(const int* __restrict__ poi_idx,
        const float* __restrict__ lat, const float* __restrict__ lon,
        const float* __restrict__ cent,
        const float* __restrict__ E_dm,
        const float* __restrict__ region_emb,
        float* __restrict__ out) {
    extern __shared__ float sm[];
    float* sRe = sm + 6600;
    float2* sEdm2 = (float2*)(sm + 23496);
    float* slh  = sm + 23624;
    float* sloh = sm + 23688;
    float* scs  = sm + 23752;
    int* spad   = (int*)(sm + 23816);

    const int b = blockIdx.y;
    const int r0 = blockIdx.x * 128;
    const int tid = threadIdx.x;

    if (tid < 64) sEdm2[tid] = make_float2(E_dm[tid], E_dm[min(tid + 1, 63)]);
    if (tid < 50) {
        float la = lat[b * 50 + tid];
        float lo = lon[b * 50 + tid];
        slh[tid]  = la * HALF_D2R;
        sloh[tid] = lo * HALF_D2R;
        scs[tid]  = cos_small(la * DEG2RAD_F);
        spad[tid] = (poi_idx[b * 50 + tid] < 0);
    }
    // stage S into pair-interleaved layout
    const float* gS = g_S + b * 6400;
    for (int idx = tid; idx < 6400; idx += 128) {
        int n = idx >> 7, d = idx & 127;
        sm[(n >> 1) * 264 + (d >> 2) * 8 + (n & 1) * 4 + (d & 3)] = gS[idx];
    }
    // stage region tile [128 r][128 d] -> sRe stride 132, coalesced float4
    for (int idx = tid; idx < 4096; idx += 128) {
        int row = idx >> 5, c4 = (idx & 31) * 4;
        int r = min(r0 + row, 999);
        float4 v = *(const float4*)(region_emb + r * 128 + c4);
        *(float4*)(sRe + row * 132 + c4) = v;
    }
    __syncthreads();

    const int rl = tid >> 1;            // 0..63
    const int half = tid & 1;
    const float* sp = sm + half * 4;    // (n=2i+half, d0) -> sp + i*264 + d0*2
    const float* rrow0 = sRe + rl * 132;
    const float* rrow1 = sRe + (rl + 64) * 132;

    ull acc2[25][2];
#pragma unroll
    for (int i = 0; i < 25; i++) { acc2[i][0] = 0ull; acc2[i][1] = 0ull; }

    for (int d0 = 0; d0 < 128; d0 += 4) {
        ulonglong2 re0 = *(const ulonglong2*)(rrow0 + d0);
        ulonglong2 re1 = *(const ulonglong2*)(rrow1 + d0);
#pragma unroll
        for (int i = 0; i < 25; i++) {
            ulonglong2 s = *(const ulonglong2*)(sp + i * 264 + d0 * 2);
            ull a = acc2[i][0];
            a = fma2(s.x, re0.x, a);
            a = fma2(s.y, re0.y, a);
            acc2[i][0] = a;
            ull c = acc2[i][1];
            c = fma2(s.x, re1.x, c);
            c = fma2(s.y, re1.y, c);
            acc2[i][1] = c;
        }
    }

    // epilogue per r-slot: bias + masked softmax over n, fused weighted sum
#pragma unroll
    for (int p = 0; p < 2; p++) {
        const int r = r0 + rl + 64 * p;
        const int rc = min(r, 999);
        float accf[25];
#pragma unroll
        for (int i = 0; i < 25; i++) accf[i] = unpack_sum(acc2[i][p]);

        float cla = cent[rc * 2], clo = cent[rc * 2 + 1];
        float claH = cla * HALF_D2R, cloH = clo * HALF_D2R;
        float cc = cos_small(cla * DEG2RAD_F);
        float mx = -INFINITY;
#pragma unroll
        for (int i = 0; i < 25; i++) {
            int n = 2 * i + half;
            float dd = hav_km(claH - slh[n], cloH - sloh[n], cc * scs[n]);
            float bias = interp2(sEdm2, dd * (63.0f / 200.0f));
            float sc = fmaf(accf[i], INV_SQRT_D, bias);
            if (spad[n]) sc = -INFINITY;
            accf[i] = sc;
            mx = fmaxf(mx, sc);
        }
        mx = fmaxf(mx, __shfl_xor_sync(0xffffffffu, mx, 1));

        float sum = 0.f, ws = 0.f;
        if (mx != -INFINITY) {
#pragma unroll
            for (int i = 0; i < 25; i++) {
                int n = 2 * i + half;
                if (!spad[n]) {
                    float e = __expf(accf[i] - mx);
                    sum += e;
                    ws = fmaf(e, accf[i], ws);
                }
            }
        }
        sum += __shfl_xor_sync(0xffffffffu, sum, 1);
        ws  += __shfl_xor_sync(0xffffffffu, ws, 1);
        if (half == 0 && r < 1000)
            out[b * 1000 + r] = (sum > 0.f) ? ws / sum : 0.f;
    }
}

#define SMEM1_BYTES (25664 * 4)
#define SMEM2_BYTES (23880 * 4)

extern "C" void kernel_launch(void* const* d_in, const int* in_sizes, int n_in,
                              void* d_out, int out_size) {
    const int*   poi  = (const int*)  d_in[0];
    const int*   hr   = (const int*)  d_in[1];
    const float* lat  = (const float*)d_in[2];
    const float* lon  = (const float*)d_in[3];
    const float* tmin = (const float*)d_in[4];
    const float* cent = (const float*)d_in[5];
    const float* pemb = (const float*)d_in[6];
    const float* temb = (const float*)d_in[7];
    const float* Et   = (const float*)d_in[8];
    const float* Ed   = (const float*)d_in[9];
    const float* Edm  = (const float*)d_in[10];
    const float* remb = (const float*)d_in[11];
    const float* Wq   = (const float*)d_in[12];
    const float* Wk   = (const float*)d_in[13];
    const float* Wv   = (const float*)d_in[14];
    float* out = (float*)d_out;

    cudaFuncSetAttribute(stan_k1, cudaFuncAttributeMaxDynamicSharedMemorySize, SMEM1_BYTES);
    cudaFuncSetAttribute(stan_k2, cudaFuncAttributeMaxDynamicSharedMemorySize, SMEM2_BYTES);

    stan_kM<<<128, 128>>>(Wq, Wk);
    stan_k1<<<1024, 256, SMEM1_BYTES>>>(poi, hr, lat, lon, tmin,
                                        pemb, temb, Et, Ed, Wv);
    stan_k2<<<dim3(8, 1024), 128, SMEM2_BYTES>>>(poi, lat, lon, cent, Edm, remb, out);
}